// round 5
// baseline (speedup 1.0000x reference)
#include <cuda_runtime.h>
#include <cuda_bf16.h>
#include <cstdint>

#define N_NODES   50000
#define N_EDGES   800000
#define D_FEAT    128
#define HIDDEN    256
#define N_PAD     50048          // 391 * 128
#define M_TILES   391

// ---------------- scratch (static device globals) ---------------------------
__device__ int   g_deg[N_NODES];
__device__ int   g_rowptr[N_NODES + 1];
__device__ int   g_cursor[N_NODES];
__device__ float g_invdeg[N_NODES];
__device__ int   g_nbr[N_EDGES];
__device__ __nv_bfloat16 g_Ahi[(size_t)N_PAD * 256];   // [mean|x] hi; pad rows stay 0
__device__ __nv_bfloat16 g_Alo[(size_t)N_PAD * 256];
__device__ __nv_bfloat16 g_Bhi[256 * 256];             // B^T: [n][k], k-major
__device__ __nv_bfloat16 g_Blo[256 * 256];
__device__ float g_p[N_NODES * 2];   // h @ W2l (atomic-accumulated)
__device__ float g_q[N_NODES * 2];   // h @ W2r

__device__ __forceinline__ uint32_t smem_u32(const void* p) {
    uint32_t a;
    asm("{ .reg .u64 t; cvta.to.shared.u64 t, %1; cvt.u32.u64 %0, t; }" : "=r"(a) : "l"(p));
    return a;
}

// ---------------- CSR build --------------------------------------------------
__global__ void k_zero() {
    int i = blockIdx.x * blockDim.x + threadIdx.x;
    if (i < N_NODES) g_deg[i] = 0;
    if (i < N_NODES * 2) { g_p[i] = 0.f; g_q[i] = 0.f; }
}
__global__ void k_hist(const int* __restrict__ dst) {
    int e = blockIdx.x * blockDim.x + threadIdx.x;
    if (e < N_EDGES) atomicAdd(&g_deg[dst[e]], 1);
}

// 1 block, 1024 threads, thread-coarsened 2-pass scan (CH=49 elems/thread)
__global__ void k_scan() {
    const int CH = 49;                 // 1024*49 = 50176 >= N_NODES
    __shared__ int warp_tot[32];
    int tid = threadIdx.x, lane = tid & 31, wid = tid >> 5;
    int start = tid * CH;
    int s = 0;
#pragma unroll 7
    for (int i = 0; i < CH; i++) {
        int idx = start + i;
        if (idx < N_NODES) s += g_deg[idx];
    }
    // block exclusive scan of per-thread sums
    int xv = s;
#pragma unroll
    for (int o = 1; o < 32; o <<= 1) {
        int t = __shfl_up_sync(0xffffffffu, xv, o);
        if (lane >= o) xv += t;
    }
    if (lane == 31) warp_tot[wid] = xv;
    __syncthreads();
    if (wid == 0) {
        int w = warp_tot[lane];
#pragma unroll
        for (int o = 1; o < 32; o <<= 1) {
            int t = __shfl_up_sync(0xffffffffu, w, o);
            if (lane >= o) w += t;
        }
        warp_tot[lane] = w;
    }
    __syncthreads();
    int prefix = xv - s + ((wid > 0) ? warp_tot[wid - 1] : 0);
    int run = prefix;
#pragma unroll 7
    for (int i = 0; i < CH; i++) {
        int idx = start + i;
        if (idx < N_NODES) {
            int v = g_deg[idx];
            g_rowptr[idx] = run;
            g_cursor[idx] = run;
            g_invdeg[idx] = 1.0f / (float)(v > 0 ? v : 1);
            run += v;
        }
    }
    if (tid == 1023) g_rowptr[N_NODES] = run;
}
__global__ void k_scatter(const int* __restrict__ src, const int* __restrict__ dst) {
    int e = blockIdx.x * blockDim.x + threadIdx.x;
    if (e < N_EDGES) {
        int d = dst[e];
        int pos = atomicAdd(&g_cursor[d], 1);
        g_nbr[pos] = src[e];
    }
}

// ---------------- bf16 split helpers ----------------------------------------
__device__ __forceinline__ void split_bf16(float v, unsigned short& h, unsigned short& l) {
    __nv_bfloat16 bh = __float2bfloat16_rn(v);
    float r = v - __bfloat162float(bh);
    __nv_bfloat16 bl = __float2bfloat16_rn(r);
    h = __bfloat16_as_ushort(bh);
    l = __bfloat16_as_ushort(bl);
}

// agg layer1 (warp/node) + convert mean to bf16 hi/lo into A cols [0,128)
__global__ void k_agg1c(const float* __restrict__ x) {
    int warp = (blockIdx.x * blockDim.x + threadIdx.x) >> 5;
    int lane = threadIdx.x & 31;
    if (warp >= N_NODES) return;
    int beg = g_rowptr[warp], end = g_rowptr[warp + 1];
    float4 acc = make_float4(0.f, 0.f, 0.f, 0.f);
    for (int j = beg; j < end; j++) {
        int s = g_nbr[j];
        float4 v = *(const float4*)(x + (size_t)s * D_FEAT + lane * 4);
        acc.x += v.x; acc.y += v.y; acc.z += v.z; acc.w += v.w;
    }
    float id = g_invdeg[warp];
    acc.x *= id; acc.y *= id; acc.z *= id; acc.w *= id;
    unsigned short h0, h1, h2, h3, l0, l1, l2, l3;
    split_bf16(acc.x, h0, l0); split_bf16(acc.y, h1, l1);
    split_bf16(acc.z, h2, l2); split_bf16(acc.w, h3, l3);
    uint2 ph, pl;
    ph.x = (uint32_t)h0 | ((uint32_t)h1 << 16);
    ph.y = (uint32_t)h2 | ((uint32_t)h3 << 16);
    pl.x = (uint32_t)l0 | ((uint32_t)l1 << 16);
    pl.y = (uint32_t)l2 | ((uint32_t)l3 << 16);
    size_t off = (size_t)warp * 256 + lane * 4;
    *reinterpret_cast<uint2*>(&g_Ahi[off]) = ph;
    *reinterpret_cast<uint2*>(&g_Alo[off]) = pl;
}

// convert x into A cols [128,256)
__global__ void k_convx(const float* __restrict__ x) {
    int i = blockIdx.x * blockDim.x + threadIdx.x;
    if (i >= N_NODES * 32) return;
    int node = i >> 5, lane = i & 31;
    float4 v = *(const float4*)(x + (size_t)node * D_FEAT + lane * 4);
    unsigned short h0, h1, h2, h3, l0, l1, l2, l3;
    split_bf16(v.x, h0, l0); split_bf16(v.y, h1, l1);
    split_bf16(v.z, h2, l2); split_bf16(v.w, h3, l3);
    uint2 ph, pl;
    ph.x = (uint32_t)h0 | ((uint32_t)h1 << 16);
    ph.y = (uint32_t)h2 | ((uint32_t)h3 << 16);
    pl.x = (uint32_t)l0 | ((uint32_t)l1 << 16);
    pl.y = (uint32_t)l2 | ((uint32_t)l3 << 16);
    size_t off = (size_t)node * 256 + 128 + lane * 4;
    *reinterpret_cast<uint2*>(&g_Ahi[off]) = ph;
    *reinterpret_cast<uint2*>(&g_Alo[off]) = pl;
}

// B^T build: g_B[n][k] = W1[k][n], W1 = [W1l ; W1r]
__global__ void k_convW(const float* __restrict__ W1l, const float* __restrict__ W1r) {
    int i = blockIdx.x * blockDim.x + threadIdx.x;
    if (i >= 256 * 256) return;
    int k = i >> 8, n = i & 255;
    float v = (k < 128) ? W1l[k * 256 + n] : W1r[(k - 128) * 256 + n];
    unsigned short h, l;
    split_bf16(v, h, l);
    g_Bhi[n * 256 + k] = __ushort_as_bfloat16(h);
    g_Blo[n * 256 + k] = __ushort_as_bfloat16(l);
}

// ---------------- HMMA GEMM1 (cp.async + ldmatrix) ---------------------------
// block tile 128(M) x 128(N), 8 warps = 4(M) x 2(N), warp tile 32x64
// K: 4 chunks of 64, double-buffered. smem row stride: 144B (72 halves).
#define SA_HI   0
#define SA_LO   18432
#define SB_HI   36864
#define SB_LO   55296
#define STAGE_SZ 73728
#define SBIAS   147456    // 128 f32
#define SW2L    147968    // 128 float2
#define SW2R    148992    // 128 float2
#define SM_TOT  150016

#define CP16(dst, src) asm volatile("cp.async.cg.shared.global [%0], [%1], 16;" \
    :: "r"(dst), "l"(src))
#define CP_COMMIT() asm volatile("cp.async.commit_group;")

__device__ __forceinline__ void ldm_x4(uint32_t* r, uint32_t addr) {
    asm volatile("ldmatrix.sync.aligned.m8n8.x4.shared.b16 {%0,%1,%2,%3}, [%4];"
        : "=r"(r[0]), "=r"(r[1]), "=r"(r[2]), "=r"(r[3]) : "r"(addr));
}
__device__ __forceinline__ void mma_bf16(float* d, const uint32_t* a,
                                         uint32_t b0, uint32_t b1) {
    asm volatile(
        "mma.sync.aligned.m16n8k16.row.col.f32.bf16.bf16.f32 "
        "{%0,%1,%2,%3}, {%4,%5,%6,%7}, {%8,%9}, {%0,%1,%2,%3};"
        : "+f"(d[0]), "+f"(d[1]), "+f"(d[2]), "+f"(d[3])
        : "r"(a[0]), "r"(a[1]), "r"(a[2]), "r"(a[3]), "r"(b0), "r"(b1));
}

__global__ void __launch_bounds__(256, 1)
k_gemm1_mma(const float* __restrict__ b1,
            const float* __restrict__ W2l, const float* __restrict__ W2r,
            float* __restrict__ h) {
    extern __shared__ char smem[];
    uint32_t sb = smem_u32(smem);
    int tid  = threadIdx.x, lane = tid & 31, warp = tid >> 5;
    int warpM = warp & 3, warpN = warp >> 2;
    int m0 = blockIdx.x * 128, n0 = blockIdx.y * 128;

    float*  bias = (float*)(smem + SBIAS);
    float2* w2l  = (float2*)(smem + SW2L);
    float2* w2r  = (float2*)(smem + SW2R);
    if (tid < 128) {
        bias[tid] = b1[n0 + tid];
        w2l[tid]  = ((const float2*)W2l)[n0 + tid];
        w2r[tid]  = ((const float2*)W2r)[n0 + tid];
    }

    size_t gAhi = __cvta_generic_to_global(g_Ahi);
    size_t gAlo = __cvta_generic_to_global(g_Alo);
    size_t gBhi = __cvta_generic_to_global(g_Bhi);
    size_t gBlo = __cvta_generic_to_global(g_Blo);

    // per-thread load coords (16B granules): 1024 granules / array / chunk
    int lr = 0, lq = 0;
    {
        // each thread does 4 granules: idx = tid + t*256
    }

    float acc[2][8][4];
#pragma unroll
    for (int mt = 0; mt < 2; mt++)
#pragma unroll
        for (int nt = 0; nt < 8; nt++)
#pragma unroll
            for (int j = 0; j < 4; j++) acc[mt][nt][j] = 0.f;

    // ---- load chunk helper (macro to keep everything in registers) ----
#define LOAD_CHUNK(ST, C) do {                                                 \
    uint32_t sbase = sb + (ST) * STAGE_SZ;                                     \
    _Pragma("unroll")                                                          \
    for (int t = 0; t < 4; t++) {                                              \
        int idx = tid + t * 256;                                               \
        int r = idx >> 3, q = idx & 7;                                         \
        size_t eo = ((size_t)(C) * 64 + q * 8) * 2;                            \
        size_t ga = ((size_t)(m0 + r) * 256) * 2 + eo;                         \
        size_t gb = ((size_t)(n0 + r) * 256) * 2 + eo;                         \
        uint32_t so = (uint32_t)(r * 144 + q * 16);                            \
        CP16(sbase + SA_HI + so, gAhi + ga);                                   \
        CP16(sbase + SA_LO + so, gAlo + ga);                                   \
        CP16(sbase + SB_HI + so, gBhi + gb);                                   \
        CP16(sbase + SB_LO + so, gBlo + gb);                                   \
    }                                                                          \
    CP_COMMIT();                                                               \
} while (0)

    (void)lr; (void)lq;
    LOAD_CHUNK(0, 0);

#pragma unroll 1
    for (int c = 0; c < 4; c++) {
        if (c < 3) {
            LOAD_CHUNK((c + 1) & 1, c + 1);
            asm volatile("cp.async.wait_group 1;");
        } else {
            asm volatile("cp.async.wait_group 0;");
        }
        __syncthreads();
        uint32_t stage = sb + (c & 1) * STAGE_SZ;

#pragma unroll
        for (int s = 0; s < 4; s++) {
            // A fragments: row = warpM*32 + mt*16 + lane%16, k halves = s*16 + (lane/16)*8
            uint32_t ah[2][4], al[2][4];
#pragma unroll
            for (int mt = 0; mt < 2; mt++) {
                int row = warpM * 32 + mt * 16 + (lane & 15);
                uint32_t off = (uint32_t)(row * 144 + (s * 16 + (lane >> 4) * 8) * 2);
                ldm_x4(ah[mt], stage + SA_HI + off);
                ldm_x4(al[mt], stage + SA_LO + off);
            }
            // B fragments: 4 pairs of 16 n
            uint32_t bh[4][4], bl[4][4];
#pragma unroll
            for (int pr = 0; pr < 4; pr++) {
                int nrow = warpN * 64 + pr * 16 + ((lane >> 4) ? 8 : 0) + (lane & 7);
                int koff = s * 16 + (((lane >> 3) & 1) * 8);
                uint32_t off = (uint32_t)(nrow * 144 + koff * 2);
                ldm_x4(bh[pr], stage + SB_HI + off);
                ldm_x4(bl[pr], stage + SB_LO + off);
            }
#pragma unroll
            for (int pr = 0; pr < 4; pr++) {
#pragma unroll
                for (int hf = 0; hf < 2; hf++) {
                    int nt = pr * 2 + hf;
                    uint32_t bh0 = bh[pr][hf * 2], bh1 = bh[pr][hf * 2 + 1];
                    uint32_t bl0 = bl[pr][hf * 2], bl1 = bl[pr][hf * 2 + 1];
#pragma unroll
                    for (int mt = 0; mt < 2; mt++) {
                        mma_bf16(acc[mt][nt], ah[mt], bh0, bh1);
                        mma_bf16(acc[mt][nt], ah[mt], bl0, bl1);
                        mma_bf16(acc[mt][nt], al[mt], bh0, bh1);
                    }
                }
            }
        }
        __syncthreads();
    }

    // epilogue: bias + relu + store h; fused projections p = h@W2l, q = h@W2r
#pragma unroll
    for (int mt = 0; mt < 2; mt++) {
        int rowA = m0 + warpM * 32 + mt * 16 + (lane >> 2);
        int rowB = rowA + 8;
        float pla0 = 0.f, pla1 = 0.f, pra0 = 0.f, pra1 = 0.f;
        float plb0 = 0.f, plb1 = 0.f, prb0 = 0.f, prb1 = 0.f;
#pragma unroll
        for (int nt = 0; nt < 8; nt++) {
            int cl = warpN * 64 + nt * 8 + (lane & 3) * 2;
            float bz0 = bias[cl], bz1 = bias[cl + 1];
            float h0 = fmaxf(acc[mt][nt][0] + bz0, 0.f);
            float h1 = fmaxf(acc[mt][nt][1] + bz1, 0.f);
            float h2 = fmaxf(acc[mt][nt][2] + bz0, 0.f);
            float h3 = fmaxf(acc[mt][nt][3] + bz1, 0.f);
            if (rowA < N_NODES)
                *(float2*)(h + (size_t)rowA * 256 + n0 + cl) = make_float2(h0, h1);
            if (rowB < N_NODES)
                *(float2*)(h + (size_t)rowB * 256 + n0 + cl) = make_float2(h2, h3);
            float2 wl0 = w2l[cl], wl1 = w2l[cl + 1];
            float2 wr0 = w2r[cl], wr1 = w2r[cl + 1];
            pla0 += h0 * wl0.x + h1 * wl1.x;  pla1 += h0 * wl0.y + h1 * wl1.y;
            pra0 += h0 * wr0.x + h1 * wr1.x;  pra1 += h0 * wr0.y + h1 * wr1.y;
            plb0 += h2 * wl0.x + h3 * wl1.x;  plb1 += h2 * wl0.y + h3 * wl1.y;
            prb0 += h2 * wr0.x + h3 * wr1.x;  prb1 += h2 * wr0.y + h3 * wr1.y;
        }
#pragma unroll
        for (int o = 1; o <= 2; o <<= 1) {
            pla0 += __shfl_xor_sync(0xffffffffu, pla0, o);
            pla1 += __shfl_xor_sync(0xffffffffu, pla1, o);
            pra0 += __shfl_xor_sync(0xffffffffu, pra0, o);
            pra1 += __shfl_xor_sync(0xffffffffu, pra1, o);
            plb0 += __shfl_xor_sync(0xffffffffu, plb0, o);
            plb1 += __shfl_xor_sync(0xffffffffu, plb1, o);
            prb0 += __shfl_xor_sync(0xffffffffu, prb0, o);
            prb1 += __shfl_xor_sync(0xffffffffu, prb1, o);
        }
        if ((lane & 3) == 0) {
            if (rowA < N_NODES) {
                atomicAdd(&g_p[rowA * 2 + 0], pla0);
                atomicAdd(&g_p[rowA * 2 + 1], pla1);
                atomicAdd(&g_q[rowA * 2 + 0], pra0);
                atomicAdd(&g_q[rowA * 2 + 1], pra1);
            }
            if (rowB < N_NODES) {
                atomicAdd(&g_p[rowB * 2 + 0], plb0);
                atomicAdd(&g_p[rowB * 2 + 1], plb1);
                atomicAdd(&g_q[rowB * 2 + 0], prb0);
                atomicAdd(&g_q[rowB * 2 + 1], prb1);
            }
        }
    }
}

// ---------------- layer-2: aggregate p, add q, sigmoid, store ----------------
__global__ void k_aggout(const float* __restrict__ b2, float* __restrict__ out) {
    int i = blockIdx.x * blockDim.x + threadIdx.x;
    if (i >= N_NODES) return;
    int beg = g_rowptr[i], end = g_rowptr[i + 1];
    float a0 = 0.f, a1 = 0.f;
    const float2* p2 = (const float2*)g_p;
    for (int j = beg; j < end; j++) {
        float2 v = p2[g_nbr[j]];
        a0 += v.x; a1 += v.y;
    }
    float id = g_invdeg[i];
    float v0 = a0 * id + g_q[i * 2 + 0] + b2[0];
    float v1 = a1 * id + g_q[i * 2 + 1] + b2[1];
    out[i * 2 + 0] = 1.0f / (1.0f + __expf(-v0));
    out[i * 2 + 1] = 1.0f / (1.0f + __expf(-v1));
}

// ---------------- launch ------------------------------------------------------
extern "C" void kernel_launch(void* const* d_in, const int* in_sizes, int n_in,
                              void* d_out, int out_size) {
    const float* x   = (const float*)d_in[0];
    const int*   ei  = (const int*)d_in[1];
    const float* W1l = (const float*)d_in[2];
    const float* W1r = (const float*)d_in[3];
    const float* b1  = (const float*)d_in[4];
    const float* W2l = (const float*)d_in[5];
    const float* W2r = (const float*)d_in[6];
    const float* b2  = (const float*)d_in[7];

    float* out = (float*)d_out;
    float* emb = out + (size_t)N_NODES * 2;

    const int* src = ei;
    const int* dst = ei + N_EDGES;

    cudaFuncSetAttribute(k_gemm1_mma, cudaFuncAttributeMaxDynamicSharedMemorySize, SM_TOT);

    // conversions + zeroing (independent of CSR)
    k_convW<<<(256 * 256 + 255) / 256, 256>>>(W1l, W1r);
    k_convx<<<(N_NODES * 32 + 255) / 256, 256>>>(x);
    k_zero<<<(N_NODES * 2 + 255) / 256, 256>>>();

    // CSR build
    k_hist<<<(N_EDGES + 255) / 256, 256>>>(dst);
    k_scan<<<1, 1024>>>();
    k_scatter<<<(N_EDGES + 255) / 256, 256>>>(src, dst);

    // layer 1 aggregation + A conversion
    k_agg1c<<<(N_NODES + 7) / 8, 256>>>(x);

    // layer-1 GEMM (HMMA, pipelined) + fused layer-2 projections
    dim3 g1(M_TILES, 2);
    k_gemm1_mma<<<g1, 256, SM_TOT>>>(b1, W2l, W2r, emb);

    // layer-2: aggregate 2-dim projections + output
    k_aggout<<<(N_NODES + 255) / 256, 256>>>(b2, out);
}